// round 1
// baseline (speedup 1.0000x reference)
#include <cuda_runtime.h>
#include <cuda_bf16.h>
#include <math.h>

// Problem constants (fixed shapes for this problem instance)
#define BB   64     // batch
#define LQ   32     // query length
#define LD   256    // doc length
#define DD   128    // feature dim
#define NN   2      // num docs per query

#define PADW 132    // padded row width (words) for conflict-free float4 smem reads

// Scratch (device globals; no allocation allowed)
__device__ float g_qn[BB * LQ * DD];          // normalized q            (1 MB)
__device__ float g_inv[NN * BB * DD];         // inverse norms over Ld   (64 KB)
__device__ float g_S[NN * BB * BB];           // MaxSim scores S[n,bq,bd] (32 KB)

// ---------------------------------------------------------------------------
// Kernel 1: L2-normalize q over the feature dim. One warp per (b, l) row.
// grid = (B*LQ/8) blocks x 256 threads
// ---------------------------------------------------------------------------
__global__ void qnorm_kernel(const float* __restrict__ q) {
    int row  = blockIdx.x * 8 + (threadIdx.x >> 5);
    int lane = threadIdx.x & 31;
    const float4* src = (const float4*)(q + (size_t)row * DD);
    float4 v = src[lane];
    float ss = v.x * v.x + v.y * v.y + v.z * v.z + v.w * v.w;
    #pragma unroll
    for (int o = 16; o; o >>= 1) ss += __shfl_xor_sync(0xffffffffu, ss, o);
    float inv = 1.0f / fmaxf(sqrtf(ss), 1e-12f);
    float4 o4 = make_float4(v.x * inv, v.y * inv, v.z * inv, v.w * inv);
    ((float4*)(g_qn + (size_t)row * DD))[lane] = o4;
}

// ---------------------------------------------------------------------------
// Kernel 2: per-feature inverse norms over the SEQUENCE axis (Ld) of masked d.
// grid = N*B blocks x 128 threads (thread = feature dd)
// ---------------------------------------------------------------------------
__global__ void dinv_kernel(const float* __restrict__ d, const int* __restrict__ mask) {
    int blk = blockIdx.x;            // n*B + b
    int dd  = threadIdx.x;
    const float* base = d + (size_t)blk * LD * DD;
    const int*   mb   = mask + (size_t)blk * LD;
    float acc = 0.0f;
    for (int m = 0; m < LD; m++) {
        float x = base[(size_t)m * DD + dd] * (float)mb[m];
        acc += x * x;
    }
    g_inv[(size_t)blk * DD + dd] = 1.0f / fmaxf(sqrtf(acc), 1e-12f);
}

// ---------------------------------------------------------------------------
// Kernel 3: MaxSim. One block per (n, bd). d tile cached in smem (masked +
// normalized on load), loop over bq pairs; 64x256 output tile per iteration
// with 4x8 register tiling per thread; warp-shuffle row-max epilogue.
// grid = N*B blocks x 512 threads, dynamic smem = (LD+64)*PADW*4 bytes
// ---------------------------------------------------------------------------
__global__ void __launch_bounds__(512, 1)
maxsim_kernel(const float* __restrict__ d_reps, const int* __restrict__ d_masks) {
    extern __shared__ float smem[];
    float* d_s = smem;                 // [LD][PADW]
    float* q_s = smem + LD * PADW;     // [64][PADW]
    __shared__ float s_sum[2];

    const int tid = threadIdx.x;
    const int tc  = tid & 31;          // col group (32)
    const int tr  = tid >> 5;          // row group (16)
    const int blk = blockIdx.x;        // n*B + bd
    const int n   = blk >> 6;
    const int bd  = blk & 63;

    // --- load + scale d tile: d_s[m][dd] = d[n,bd,m,dd] * mask * inv_norm ---
    const float4* dsrc = (const float4*)(d_reps + (size_t)blk * LD * DD);
    const int*    mrow = d_masks + (size_t)blk * LD;
    const float4* inv4 = (const float4*)(g_inv + (size_t)blk * DD);
    for (int f = tid; f < LD * (DD / 4); f += 512) {
        int m  = f >> 5;               // row (Ld index)
        int c4 = f & 31;               // float4 column within row
        float4 v  = dsrc[f];
        float  mk = (float)mrow[m];
        float4 iv = inv4[c4];
        v.x *= mk * iv.x;  v.y *= mk * iv.y;
        v.z *= mk * iv.z;  v.w *= mk * iv.w;
        *(float4*)(d_s + m * PADW + c4 * 4) = v;
    }

    for (int it = 0; it < BB / 2; ++it) {
        const int bq0 = it * 2;
        __syncthreads();   // prior compute done (and d_s ready on first iter)

        // load q tile for 2 queries: q_s[r][k], r in [0,64)
        const float4* qsrc = (const float4*)g_qn + (size_t)bq0 * LQ * (DD / 4);
        for (int f = tid; f < 64 * (DD / 4); f += 512) {
            int r = f >> 5, k4 = f & 31;
            *(float4*)(q_s + r * PADW + k4 * 4) = qsrc[f];
        }
        if (tid < 2) s_sum[tid] = 0.0f;
        __syncthreads();

        // ---- 64x256 fp32 GEMM fragment, 4 rows x 8 cols per thread ----
        float acc[4][8];
        #pragma unroll
        for (int i = 0; i < 4; i++)
            #pragma unroll
            for (int j = 0; j < 8; j++) acc[i][j] = 0.0f;

        #pragma unroll 2
        for (int k = 0; k < DD; k += 4) {
            float4 qv[4];
            #pragma unroll
            for (int i = 0; i < 4; i++)
                qv[i] = *(const float4*)(q_s + (tr * 4 + i) * PADW + k);
            float4 dv[8];
            #pragma unroll
            for (int j = 0; j < 8; j++)
                dv[j] = *(const float4*)(d_s + (tc + 32 * j) * PADW + k);
            #pragma unroll
            for (int i = 0; i < 4; i++) {
                #pragma unroll
                for (int j = 0; j < 8; j++) {
                    acc[i][j] = fmaf(qv[i].x, dv[j].x, acc[i][j]);
                    acc[i][j] = fmaf(qv[i].y, dv[j].y, acc[i][j]);
                    acc[i][j] = fmaf(qv[i].z, dv[j].z, acc[i][j]);
                    acc[i][j] = fmaf(qv[i].w, dv[j].w, acc[i][j]);
                }
            }
        }

        // ---- epilogue: per-row max over 256 cols, then sum over rows ----
        float rowsum = 0.0f;
        #pragma unroll
        for (int i = 0; i < 4; i++) {
            float m = acc[i][0];
            #pragma unroll
            for (int j = 1; j < 8; j++) m = fmaxf(m, acc[i][j]);
            #pragma unroll
            for (int o = 16; o; o >>= 1)
                m = fmaxf(m, __shfl_xor_sync(0xffffffffu, m, o));
            rowsum += m;  // only lane 0's value is used
        }
        if (tc == 0) atomicAdd(&s_sum[tr >> 3], rowsum);
        __syncthreads();

        if (tid < 2) {
            int bq = bq0 + tid;
            g_S[((size_t)n * BB + bq) * BB + bd] = s_sum[tid];
        }
    }
}

// ---------------------------------------------------------------------------
// Kernel 4: loss finalize (KL + 0.5 * CE). Single block, 128 threads.
// ---------------------------------------------------------------------------
__global__ void finalize_kernel(const float* __restrict__ labels, float* __restrict__ out) {
    __shared__ float sh[4];
    const int tid  = threadIdx.x;   // 128 threads
    const int lane = tid & 31;
    const int w    = tid >> 5;
    double kl = 0.0, ce = 0.0;

    for (int bq = 0; bq < BB; bq++) {
        int nn = tid >> 6;
        int bd = tid & 63;
        float v = g_S[((size_t)nn * BB + bq) * BB + bd];

        // block max over 128 values
        float m = v;
        #pragma unroll
        for (int o = 16; o; o >>= 1) m = fmaxf(m, __shfl_xor_sync(0xffffffffu, m, o));
        if (lane == 0) sh[w] = m;
        __syncthreads();
        float bmax = fmaxf(fmaxf(sh[0], sh[1]), fmaxf(sh[2], sh[3]));
        __syncthreads();

        // block sum of exp
        float e = expf(v - bmax);
        #pragma unroll
        for (int o = 16; o; o >>= 1) e += __shfl_xor_sync(0xffffffffu, e, o);
        if (lane == 0) sh[w] = e;
        __syncthreads();

        if (tid == 0) {
            double tot  = (double)sh[0] + sh[1] + sh[2] + sh[3];
            double lse  = (double)bmax + log(tot);
            double s0   = g_S[((size_t)0 * BB + bq) * BB + bq];
            double s1   = g_S[((size_t)1 * BB + bq) * BB + bq];
            ce += lse - s0;
            double m2   = fmax(s0, s1);
            double lse2 = m2 + log(exp(s0 - m2) + exp(s1 - m2));
            double l0   = labels[bq * NN + 0];
            double l1   = labels[bq * NN + 1];
            kl += exp(l0) * (l0 - (s0 - lse2)) + exp(l1) * (l1 - (s1 - lse2));
        }
        __syncthreads();
    }
    if (tid == 0) out[0] = (float)((kl + 0.5 * ce) / (double)BB);
}

// ---------------------------------------------------------------------------
extern "C" void kernel_launch(void* const* d_in, const int* in_sizes, int n_in,
                              void* d_out, int out_size) {
    const float* q_reps  = (const float*)d_in[0];   // [B, Lq, D]
    const float* d_reps  = (const float*)d_in[1];   // [N, B, Ld, D]
    const int*   d_masks = (const int*)d_in[2];     // [N, B, Ld]
    const float* labels  = (const float*)d_in[3];   // [B, N]
    float* out = (float*)d_out;

    qnorm_kernel<<<(BB * LQ) / 8, 256>>>(q_reps);
    dinv_kernel<<<NN * BB, 128>>>(d_reps, d_masks);

    const int smem_bytes = (LD + 64) * PADW * (int)sizeof(float);  // ~169 KB
    cudaFuncSetAttribute(maxsim_kernel,
                         cudaFuncAttributeMaxDynamicSharedMemorySize, smem_bytes);
    maxsim_kernel<<<NN * BB, 512, smem_bytes>>>(d_reps, d_masks);

    finalize_kernel<<<1, 128>>>(labels, out);
}

// round 3
// speedup vs baseline: 6.0295x; 6.0295x over previous
#include <cuda_runtime.h>
#include <cuda_bf16.h>
#include <math.h>
#include <stdint.h>

// Shapes (fixed)
#define BB   64
#define LQ   32
#define LD   256
#define DD   128
#define NN   2

// ---------------- scratch (no allocation allowed) ----------------
__device__ __align__(16) __nv_bfloat16 g_qbf[BB * LQ * DD];  // normalized q, bf16
__device__ float g_inv[NN * BB * DD];                        // inverse norms over Ld
__device__ float g_S[NN * BB * BB];                          // S[n,bq,bd]

__device__ __forceinline__ uint32_t smem_u32(const void* p) {
    uint32_t a;
    asm("{ .reg .u64 t; cvta.to.shared.u64 t, %1; cvt.u32.u64 %0, t; }" : "=r"(a) : "l"(p));
    return a;
}

__device__ __forceinline__ void ldsm_x4(uint32_t addr, uint32_t& r0, uint32_t& r1,
                                        uint32_t& r2, uint32_t& r3) {
    asm volatile("ldmatrix.sync.aligned.m8n8.x4.shared.b16 {%0,%1,%2,%3}, [%4];"
                 : "=r"(r0), "=r"(r1), "=r"(r2), "=r"(r3) : "r"(addr));
}

__device__ __forceinline__ void mma_bf16(float& c0, float& c1, float& c2, float& c3,
                                         uint32_t a0, uint32_t a1, uint32_t a2, uint32_t a3,
                                         uint32_t b0, uint32_t b1) {
    asm volatile(
        "mma.sync.aligned.m16n8k16.row.col.f32.bf16.bf16.f32 "
        "{%0,%1,%2,%3}, {%4,%5,%6,%7}, {%8,%9}, {%0,%1,%2,%3};"
        : "+f"(c0), "+f"(c1), "+f"(c2), "+f"(c3)
        : "r"(a0), "r"(a1), "r"(a2), "r"(a3), "r"(b0), "r"(b1));
}

// ---------------------------------------------------------------------------
// Kernel 1: normalize q over D, convert to bf16. One warp per q row.
// ---------------------------------------------------------------------------
__global__ void qnorm_kernel(const float* __restrict__ q) {
    int row  = blockIdx.x * 8 + (threadIdx.x >> 5);
    int lane = threadIdx.x & 31;
    const float4* src = (const float4*)(q + (size_t)row * DD);
    float4 v = src[lane];
    float ss = v.x * v.x + v.y * v.y + v.z * v.z + v.w * v.w;
    #pragma unroll
    for (int o = 16; o; o >>= 1) ss += __shfl_xor_sync(0xffffffffu, ss, o);
    float inv = 1.0f / fmaxf(sqrtf(ss), 1e-12f);
    __nv_bfloat162 lo = __float22bfloat162_rn(make_float2(v.x * inv, v.y * inv));
    __nv_bfloat162 hi = __float22bfloat162_rn(make_float2(v.z * inv, v.w * inv));
    uint2 pk;
    pk.x = *(uint32_t*)&lo;
    pk.y = *(uint32_t*)&hi;
    ((uint2*)(g_qbf + (size_t)row * DD))[lane] = pk;
}

// ---------------------------------------------------------------------------
// Kernel 2: per-feature inverse norms over Ld of masked d.
// ---------------------------------------------------------------------------
__global__ void dinv_kernel(const float* __restrict__ d, const int* __restrict__ mask) {
    int blk = blockIdx.x;   // n*B + b
    int dd  = threadIdx.x;
    const float* base = d + (size_t)blk * LD * DD;
    const int*   mb   = mask + (size_t)blk * LD;
    float acc = 0.0f;
    for (int m = 0; m < LD; m++) {
        float x = base[(size_t)m * DD + dd] * (float)mb[m];
        acc += x * x;
    }
    g_inv[(size_t)blk * DD + dd] = 1.0f / fmaxf(sqrtf(acc), 1e-12f);
}

// ---------------------------------------------------------------------------
// Kernel 3: HMMA MaxSim. One CTA per (n,bd), 256 threads (8 warps).
//  - smem B: d tile [256 rows x 128 bf16] (256 B rows, 16B-chunk XOR swizzle)
//  - smem A: q tile [128 rows x 128 bf16] per M-pass (16 passes)
//  - warp = 16 M-rows; N in 4 chunks of 64; k = 8 steps of 16
//  - epilogue: in-register row-max, quad/warp shuffles, smem atomicAdd per bq
// ---------------------------------------------------------------------------
#define A_BYTES  (128 * 256)     // 32 KB
#define B_BYTES  (256 * 256)     // 64 KB
#define SMEM_TOTAL (A_BYTES + B_BYTES)

__global__ void __launch_bounds__(256, 1)
maxsim_kernel(const float* __restrict__ d_reps, const int* __restrict__ d_masks) {
    extern __shared__ char smem[];
    const uint32_t Ab = smem_u32(smem);             // A tile
    const uint32_t Bb = Ab + A_BYTES;               // B tile
    __shared__ float s_bq[4];

    const int tid  = threadIdx.x;
    const int wid  = tid >> 5;
    const int lane = tid & 31;
    const int blk  = blockIdx.x;    // n*B + bd
    const int n    = blk >> 6;
    const int bd   = blk & 63;

    // ---- B tile: mask + seq-normalize + fp32->bf16, swizzled ----
    {
        const float4* dsrc = (const float4*)(d_reps + (size_t)blk * LD * DD);
        const int*    mrow = d_masks + (size_t)blk * LD;
        const float4* inv4 = (const float4*)(g_inv + (size_t)blk * DD);
        // 256 rows x 16 chunks (16B = 8 bf16 = two source float4s)
        for (int f = tid; f < 256 * 16; f += 256) {
            int row = f >> 4, c = f & 15;
            float4 v0 = dsrc[row * 32 + c * 2];
            float4 v1 = dsrc[row * 32 + c * 2 + 1];
            float  mk = (float)mrow[row];
            float4 i0 = inv4[c * 2], i1 = inv4[c * 2 + 1];
            v0.x *= mk * i0.x; v0.y *= mk * i0.y; v0.z *= mk * i0.z; v0.w *= mk * i0.w;
            v1.x *= mk * i1.x; v1.y *= mk * i1.y; v1.z *= mk * i1.z; v1.w *= mk * i1.w;
            __nv_bfloat162 p0 = __float22bfloat162_rn(make_float2(v0.x, v0.y));
            __nv_bfloat162 p1 = __float22bfloat162_rn(make_float2(v0.z, v0.w));
            __nv_bfloat162 p2 = __float22bfloat162_rn(make_float2(v1.x, v1.y));
            __nv_bfloat162 p3 = __float22bfloat162_rn(make_float2(v1.z, v1.w));
            uint32_t addr = Bb + row * 256 + (c ^ (row & 7)) * 16;
            asm volatile("st.shared.v4.b32 [%0], {%1,%2,%3,%4};"
                         :: "r"(addr), "r"(*(uint32_t*)&p0), "r"(*(uint32_t*)&p1),
                            "r"(*(uint32_t*)&p2), "r"(*(uint32_t*)&p3) : "memory");
        }
    }

    // ---- 16 M-passes of 128 q rows ----
    for (int pass = 0; pass < 16; ++pass) {
        __syncthreads();   // prior pass fully done (incl. g_S writes)
        if (tid < 4) s_bq[tid] = 0.0f;

        // load A tile (swizzled): 128 rows x 16 chunks
        {
            const uint4* qsrc = (const uint4*)(g_qbf + (size_t)pass * 128 * DD);
            for (int f = tid; f < 128 * 16; f += 256) {
                int row = f >> 4, c = f & 15;
                uint4 v = qsrc[row * 16 + c];
                uint32_t addr = Ab + row * 256 + (c ^ (row & 7)) * 16;
                asm volatile("st.shared.v4.b32 [%0], {%1,%2,%3,%4};"
                             :: "r"(addr), "r"(v.x), "r"(v.y), "r"(v.z), "r"(v.w) : "memory");
            }
        }
        __syncthreads();

        // ---- A fragments for this warp's 16 rows, all 8 k-steps ----
        uint32_t a[8][4];
        {
            int row = wid * 16 + (lane & 15);
            int coff = lane >> 4;                 // 0 or 1 (k-half)
            uint32_t rowaddr = Ab + row * 256;
            #pragma unroll
            for (int ks = 0; ks < 8; ks++) {
                int c = 2 * ks + coff;
                uint32_t addr = rowaddr + ((c ^ (row & 7)) * 16);
                ldsm_x4(addr, a[ks][0], a[ks][1], a[ks][2], a[ks][3]);
            }
        }

        float rmax0 = -INFINITY, rmax1 = -INFINITY;

        // ---- 4 N-chunks of 64 cols ----
        #pragma unroll
        for (int nc = 0; nc < 4; ++nc) {
            float acc[8][4];
            #pragma unroll
            for (int j = 0; j < 8; j++)
                #pragma unroll
                for (int i = 0; i < 4; i++) acc[j][i] = 0.0f;

            const int n0 = nc * 64;
            // B ldmatrix address pattern (x4 covers n16 x k16 = 2 n-frags)
            int nrow_l = (lane & 7) + ((lane >> 3) & 1) * 8;   // 0..15 within n16 tile
            int coff   = lane >> 4;                             // k-half

            #pragma unroll
            for (int ks = 0; ks < 8; ++ks) {
                uint32_t b[4][4];
                #pragma unroll
                for (int np = 0; np < 4; ++np) {
                    int nrow = n0 + np * 16 + nrow_l;
                    int c = 2 * ks + coff;
                    uint32_t addr = Bb + nrow * 256 + ((c ^ (nrow & 7)) * 16);
                    ldsm_x4(addr, b[np][0], b[np][1], b[np][2], b[np][3]);
                }
                #pragma unroll
                for (int np = 0; np < 4; ++np) {
                    mma_bf16(acc[2*np][0],   acc[2*np][1],   acc[2*np][2],   acc[2*np][3],
                             a[ks][0], a[ks][1], a[ks][2], a[ks][3], b[np][0], b[np][2]);
                    mma_bf16(acc[2*np+1][0], acc[2*np+1][1], acc[2*np+1][2], acc[2*np+1][3],
                             a[ks][0], a[ks][1], a[ks][2], a[ks][3], b[np][1], b[np][3]);
                }
            }
            // full-K dot products for these 64 cols done -> fold into row max
            #pragma unroll
            for (int j = 0; j < 8; j++) {
                rmax0 = fmaxf(rmax0, fmaxf(acc[j][0], acc[j][1]));
                rmax1 = fmaxf(rmax1, fmaxf(acc[j][2], acc[j][3]));
            }
        }

        // ---- reduce: max across the 4 lanes of each row quad ----
        #pragma unroll
        for (int o = 1; o <= 2; o <<= 1) {
            rmax0 = fmaxf(rmax0, __shfl_xor_sync(0xffffffffu, rmax0, o));
            rmax1 = fmaxf(rmax1, __shfl_xor_sync(0xffffffffu, rmax1, o));
        }
        // rows: lane/4 and lane/4+8 (warp's 16 rows); sum them over the warp
        float tot = ((lane & 3) == 0) ? (rmax0 + rmax1) : 0.0f;
        #pragma unroll
        for (int o = 4; o <= 16; o <<= 1)
            tot += __shfl_xor_sync(0xffffffffu, tot, o);
        if (lane == 0) atomicAdd(&s_bq[wid >> 1], tot);   // 2 warps per bq
        __syncthreads();

        if (tid < 4) {
            int bq = pass * 4 + tid;
            g_S[((size_t)n * BB + bq) * BB + bd] = s_bq[tid];
        }
    }
}

// ---------------------------------------------------------------------------
// Kernel 4: loss finalize, parallel over bq. 64 threads, 1 block.
// ---------------------------------------------------------------------------
__global__ void finalize_kernel(const float* __restrict__ labels, float* __restrict__ out) {
    __shared__ float red[2];
    const int bq = threadIdx.x;  // 64 threads

    float vmax = -INFINITY;
    #pragma unroll
    for (int nn = 0; nn < NN; nn++)
        for (int bd = 0; bd < BB; bd++)
            vmax = fmaxf(vmax, g_S[((size_t)nn * BB + bq) * BB + bd]);
    float esum = 0.0f;
    #pragma unroll
    for (int nn = 0; nn < NN; nn++)
        for (int bd = 0; bd < BB; bd++)
            esum += expf(g_S[((size_t)nn * BB + bq) * BB + bd] - vmax);
    float lse = vmax + logf(esum);

    float s0 = g_S[((size_t)0 * BB + bq) * BB + bq];
    float s1 = g_S[((size_t)1 * BB + bq) * BB + bq];
    float ce_t = lse - s0;

    float m2   = fmaxf(s0, s1);
    float lse2 = m2 + logf(expf(s0 - m2) + expf(s1 - m2));
    float l0 = labels[bq * NN + 0];
    float l1 = labels[bq * NN + 1];
    float kl_t = expf(l0) * (l0 - (s0 - lse2)) + expf(l1) * (l1 - (s1 - lse2));

    float contrib = kl_t + 0.5f * ce_t;
    #pragma unroll
    for (int o = 16; o; o >>= 1) contrib += __shfl_xor_sync(0xffffffffu, contrib, o);
    if ((threadIdx.x & 31) == 0) red[threadIdx.x >> 5] = contrib;
    __syncthreads();
    if (threadIdx.x == 0) out[0] = (red[0] + red[1]) / (float)BB;
}

// ---------------------------------------------------------------------------
extern "C" void kernel_launch(void* const* d_in, const int* in_sizes, int n_in,
                              void* d_out, int out_size) {
    const float* q_reps  = (const float*)d_in[0];   // [B, Lq, D]
    const float* d_reps  = (const float*)d_in[1];   // [N, B, Ld, D]
    const int*   d_masks = (const int*)d_in[2];     // [N, B, Ld]
    const float* labels  = (const float*)d_in[3];   // [B, N]
    float* out = (float*)d_out;

    qnorm_kernel<<<(BB * LQ) / 8, 256>>>(q_reps);
    dinv_kernel<<<NN * BB, 128>>>(d_reps, d_masks);

    cudaFuncSetAttribute(maxsim_kernel,
                         cudaFuncAttributeMaxDynamicSharedMemorySize, SMEM_TOTAL);
    maxsim_kernel<<<NN * BB, 256, SMEM_TOTAL>>>(d_reps, d_masks);

    finalize_kernel<<<1, 64>>>(labels, out);
}

// round 4
// speedup vs baseline: 8.3245x; 1.3806x over previous
#include <cuda_runtime.h>
#include <cuda_bf16.h>
#include <math.h>
#include <stdint.h>

// Shapes (fixed)
#define BB   64
#define LQ   32
#define LD   256
#define DD   128
#define NN   2

// ---------------- scratch (no allocation allowed) ----------------
__device__ __align__(16) __nv_bfloat16 g_qbf[BB * LQ * DD];  // normalized q, bf16
__device__ float g_inv[NN * BB * DD];                        // inverse norms over Ld
__device__ float g_S[NN * BB * BB];                          // S[n,bq,bd]

__device__ __forceinline__ uint32_t smem_u32(const void* p) {
    uint32_t a;
    asm("{ .reg .u64 t; cvta.to.shared.u64 t, %1; cvt.u32.u64 %0, t; }" : "=r"(a) : "l"(p));
    return a;
}

__device__ __forceinline__ void ldsm_x4(uint32_t addr, uint32_t& r0, uint32_t& r1,
                                        uint32_t& r2, uint32_t& r3) {
    asm volatile("ldmatrix.sync.aligned.m8n8.x4.shared.b16 {%0,%1,%2,%3}, [%4];"
                 : "=r"(r0), "=r"(r1), "=r"(r2), "=r"(r3) : "r"(addr));
}

__device__ __forceinline__ void mma_bf16(float& c0, float& c1, float& c2, float& c3,
                                         uint32_t a0, uint32_t a1, uint32_t a2, uint32_t a3,
                                         uint32_t b0, uint32_t b1) {
    asm volatile(
        "mma.sync.aligned.m16n8k16.row.col.f32.bf16.bf16.f32 "
        "{%0,%1,%2,%3}, {%4,%5,%6,%7}, {%8,%9}, {%0,%1,%2,%3};"
        : "+f"(c0), "+f"(c1), "+f"(c2), "+f"(c3)
        : "r"(a0), "r"(a1), "r"(a2), "r"(a3), "r"(b0), "r"(b1));
}

// ---------------------------------------------------------------------------
// Kernel 1: normalize q over D, convert to bf16. One warp per q row.
// ---------------------------------------------------------------------------
__global__ void qnorm_kernel(const float* __restrict__ q) {
    int row  = blockIdx.x * 8 + (threadIdx.x >> 5);
    int lane = threadIdx.x & 31;
    const float4* src = (const float4*)(q + (size_t)row * DD);
    float4 v = src[lane];
    float ss = v.x * v.x + v.y * v.y + v.z * v.z + v.w * v.w;
    #pragma unroll
    for (int o = 16; o; o >>= 1) ss += __shfl_xor_sync(0xffffffffu, ss, o);
    float inv = 1.0f / fmaxf(sqrtf(ss), 1e-12f);
    __nv_bfloat162 lo = __float22bfloat162_rn(make_float2(v.x * inv, v.y * inv));
    __nv_bfloat162 hi = __float22bfloat162_rn(make_float2(v.z * inv, v.w * inv));
    uint2 pk;
    pk.x = *(uint32_t*)&lo;
    pk.y = *(uint32_t*)&hi;
    ((uint2*)(g_qbf + (size_t)row * DD))[lane] = pk;
}

// ---------------------------------------------------------------------------
// Kernel 2: per-feature inverse norms over Ld of masked d. 512 threads,
// 4-way split over Ld, smem combine.
// ---------------------------------------------------------------------------
__global__ void dinv_kernel(const float* __restrict__ d, const int* __restrict__ mask) {
    __shared__ float part[4][DD];
    int blk = blockIdx.x;            // n*B + b
    int dd  = threadIdx.x & 127;
    int seg = threadIdx.x >> 7;      // 0..3
    const float* base = d + (size_t)blk * LD * DD;
    const int*   mb   = mask + (size_t)blk * LD;
    float acc = 0.0f;
    for (int m = seg * 64; m < seg * 64 + 64; m++) {
        float x = base[(size_t)m * DD + dd] * (float)mb[m];
        acc += x * x;
    }
    part[seg][dd] = acc;
    __syncthreads();
    if (seg == 0) {
        float tot = part[0][dd] + part[1][dd] + part[2][dd] + part[3][dd];
        g_inv[(size_t)blk * DD + dd] = 1.0f / fmaxf(sqrtf(tot), 1e-12f);
    }
}

// ---------------------------------------------------------------------------
// Kernel 3: HMMA MaxSim. One CTA per (n,bd), 256 threads (8 warps).
//  - smem B: d tile [256 x 128 bf16] (64 KB), XOR-swizzled 16B chunks
//  - smem A: q tile [256 x 128 bf16], double buffered (2 x 64 KB), cp.async
//  - 8 passes of 256 M-rows; warp = 32 rows = exactly one bq
//  - epilogue fully in registers/shuffles, direct g_S store
// ---------------------------------------------------------------------------
#define ABUF_BYTES (256 * 256)                  // 64 KB per buffer
#define SMEM_TOTAL (2 * ABUF_BYTES + 256 * 256) // 192 KB
#define NPASS 8

__global__ void __launch_bounds__(256, 1)
maxsim_kernel(const float* __restrict__ d_reps, const int* __restrict__ d_masks) {
    extern __shared__ char smem[];
    const uint32_t Ab0 = smem_u32(smem);
    const uint32_t Bb  = Ab0 + 2 * ABUF_BYTES;

    const int tid  = threadIdx.x;
    const int wid  = tid >> 5;
    const int lane = tid & 31;
    const int blk  = blockIdx.x;    // n*B + bd
    const int n    = blk >> 6;
    const int bd   = blk & 63;

    // ---- prefetch A(0) via cp.async (overlaps with B-tile processing) ----
    {
        const uint4* qsrc = (const uint4*)g_qbf;   // pass 0 rows 0..255
        #pragma unroll 4
        for (int f = tid; f < 256 * 16; f += 256) {
            int row = f >> 4, c = f & 15;
            uint32_t saddr = Ab0 + row * 256 + ((c ^ (row & 7)) * 16);
            asm volatile("cp.async.cg.shared.global [%0], [%1], 16;"
                         :: "r"(saddr), "l"(qsrc + f) : "memory");
        }
        asm volatile("cp.async.commit_group;" ::: "memory");
    }

    // ---- B tile: mask + seq-normalize + fp32->bf16, swizzled ----
    {
        const float4* dsrc = (const float4*)(d_reps + (size_t)blk * LD * DD);
        const int*    mrow = d_masks + (size_t)blk * LD;
        const float4* inv4 = (const float4*)(g_inv + (size_t)blk * DD);
        for (int f = tid; f < 256 * 16; f += 256) {
            int row = f >> 4, c = f & 15;
            float4 v0 = dsrc[row * 32 + c * 2];
            float4 v1 = dsrc[row * 32 + c * 2 + 1];
            float  mk = (float)mrow[row];
            float4 i0 = inv4[c * 2], i1 = inv4[c * 2 + 1];
            v0.x *= mk * i0.x; v0.y *= mk * i0.y; v0.z *= mk * i0.z; v0.w *= mk * i0.w;
            v1.x *= mk * i1.x; v1.y *= mk * i1.y; v1.z *= mk * i1.z; v1.w *= mk * i1.w;
            __nv_bfloat162 p0 = __float22bfloat162_rn(make_float2(v0.x, v0.y));
            __nv_bfloat162 p1 = __float22bfloat162_rn(make_float2(v0.z, v0.w));
            __nv_bfloat162 p2 = __float22bfloat162_rn(make_float2(v1.x, v1.y));
            __nv_bfloat162 p3 = __float22bfloat162_rn(make_float2(v1.z, v1.w));
            uint32_t addr = Bb + row * 256 + (c ^ (row & 7)) * 16;
            asm volatile("st.shared.v4.b32 [%0], {%1,%2,%3,%4};"
                         :: "r"(addr), "r"(*(uint32_t*)&p0), "r"(*(uint32_t*)&p1),
                            "r"(*(uint32_t*)&p2), "r"(*(uint32_t*)&p3) : "memory");
        }
    }

    // ---- 8 passes of 256 q rows (8 bq each; warp w -> bq = pass*8 + w) ----
    for (int pass = 0; pass < NPASS; ++pass) {
        __syncthreads();   // all warps done with buf[(pass+1)&1] (previous pass)

        // prefetch next A tile into the other buffer
        if (pass + 1 < NPASS) {
            const uint4* qsrc = (const uint4*)(g_qbf + (size_t)(pass + 1) * 256 * DD);
            uint32_t Abn = Ab0 + ((pass + 1) & 1) * ABUF_BYTES;
            #pragma unroll 4
            for (int f = tid; f < 256 * 16; f += 256) {
                int row = f >> 4, c = f & 15;
                uint32_t saddr = Abn + row * 256 + ((c ^ (row & 7)) * 16);
                asm volatile("cp.async.cg.shared.global [%0], [%1], 16;"
                             :: "r"(saddr), "l"(qsrc + f) : "memory");
            }
            asm volatile("cp.async.commit_group;" ::: "memory");
            asm volatile("cp.async.wait_group 1;" ::: "memory");  // A(pass) done
        } else {
            asm volatile("cp.async.wait_group 0;" ::: "memory");
        }
        __syncthreads();   // A(pass) visible to all

        const uint32_t Ab = Ab0 + (pass & 1) * ABUF_BYTES;

        // ---- A fragments: this warp's 32 rows, 2 m16 tiles, 8 k-steps ----
        uint32_t a[8][2][4];
        {
            int coff = lane >> 4;                 // k-half
            #pragma unroll
            for (int mt = 0; mt < 2; mt++) {
                int row = wid * 32 + mt * 16 + (lane & 15);
                uint32_t rowaddr = Ab + row * 256;
                uint32_t sw = (uint32_t)(row & 7);
                #pragma unroll
                for (int ks = 0; ks < 8; ks++) {
                    int c = 2 * ks + coff;
                    ldsm_x4(rowaddr + ((c ^ sw) * 16),
                            a[ks][mt][0], a[ks][mt][1], a[ks][mt][2], a[ks][mt][3]);
                }
            }
        }

        float rm[2][2];
        rm[0][0] = rm[0][1] = rm[1][0] = rm[1][1] = -INFINITY;

        // ---- 4 N-chunks of 64 cols ----
        const int nrow_l = (lane & 7) + ((lane >> 3) & 1) * 8;
        const int coff   = lane >> 4;
        #pragma unroll
        for (int nc = 0; nc < 4; ++nc) {
            float acc[2][8][4];
            #pragma unroll
            for (int mt = 0; mt < 2; mt++)
                #pragma unroll
                for (int j = 0; j < 8; j++)
                    #pragma unroll
                    for (int i = 0; i < 4; i++) acc[mt][j][i] = 0.0f;

            const int n0 = nc * 64;
            #pragma unroll
            for (int ks = 0; ks < 8; ++ks) {
                uint32_t b[4][4];
                #pragma unroll
                for (int np = 0; np < 4; ++np) {
                    int nrow = n0 + np * 16 + nrow_l;
                    int c = 2 * ks + coff;
                    ldsm_x4(Bb + nrow * 256 + ((c ^ (nrow & 7)) * 16),
                            b[np][0], b[np][1], b[np][2], b[np][3]);
                }
                #pragma unroll
                for (int mt = 0; mt < 2; mt++) {
                    #pragma unroll
                    for (int np = 0; np < 4; ++np) {
                        mma_bf16(acc[mt][2*np][0],   acc[mt][2*np][1],
                                 acc[mt][2*np][2],   acc[mt][2*np][3],
                                 a[ks][mt][0], a[ks][mt][1], a[ks][mt][2], a[ks][mt][3],
                                 b[np][0], b[np][2]);
                        mma_bf16(acc[mt][2*np+1][0], acc[mt][2*np+1][1],
                                 acc[mt][2*np+1][2], acc[mt][2*np+1][3],
                                 a[ks][mt][0], a[ks][mt][1], a[ks][mt][2], a[ks][mt][3],
                                 b[np][1], b[np][3]);
                    }
                }
            }
            #pragma unroll
            for (int mt = 0; mt < 2; mt++)
                #pragma unroll
                for (int j = 0; j < 8; j++) {
                    rm[mt][0] = fmaxf(rm[mt][0], fmaxf(acc[mt][j][0], acc[mt][j][1]));
                    rm[mt][1] = fmaxf(rm[mt][1], fmaxf(acc[mt][j][2], acc[mt][j][3]));
                }
        }

        // ---- warp epilogue: quad max, then sum 32 row-maxes ----
        #pragma unroll
        for (int o = 1; o <= 2; o <<= 1) {
            rm[0][0] = fmaxf(rm[0][0], __shfl_xor_sync(0xffffffffu, rm[0][0], o));
            rm[0][1] = fmaxf(rm[0][1], __shfl_xor_sync(0xffffffffu, rm[0][1], o));
            rm[1][0] = fmaxf(rm[1][0], __shfl_xor_sync(0xffffffffu, rm[1][0], o));
            rm[1][1] = fmaxf(rm[1][1], __shfl_xor_sync(0xffffffffu, rm[1][1], o));
        }
        float tot = ((lane & 3) == 0)
                  ? (rm[0][0] + rm[0][1] + rm[1][0] + rm[1][1]) : 0.0f;
        #pragma unroll
        for (int o = 4; o <= 16; o <<= 1)
            tot += __shfl_xor_sync(0xffffffffu, tot, o);
        if (lane == 0) {
            int bq = pass * 8 + wid;
            g_S[((size_t)n * BB + bq) * BB + bd] = tot;
        }
    }
}

// ---------------------------------------------------------------------------
// Kernel 4: loss finalize. 512 threads, 8 lanes per bq (segmented shuffles).
// ---------------------------------------------------------------------------
__global__ void finalize_kernel(const float* __restrict__ labels, float* __restrict__ out) {
    __shared__ float s_loss[64];
    __shared__ float red[2];
    const int tid = threadIdx.x;       // 512
    const int bq  = tid >> 3;
    const int j   = tid & 7;

    // each lane reads 16 of the 128 scores for its bq (stride 8)
    float vmax = -INFINITY;
    #pragma unroll
    for (int nn = 0; nn < NN; nn++)
        #pragma unroll
        for (int k = 0; k < 8; k++)
            vmax = fmaxf(vmax, g_S[((size_t)nn * BB + bq) * BB + (j + 8 * k)]);
    #pragma unroll
    for (int o = 1; o <= 4; o <<= 1)
        vmax = fmaxf(vmax, __shfl_xor_sync(0xffffffffu, vmax, o));

    float esum = 0.0f;
    #pragma unroll
    for (int nn = 0; nn < NN; nn++)
        #pragma unroll
        for (int k = 0; k < 8; k++)
            esum += expf(g_S[((size_t)nn * BB + bq) * BB + (j + 8 * k)] - vmax);
    #pragma unroll
    for (int o = 1; o <= 4; o <<= 1)
        esum += __shfl_xor_sync(0xffffffffu, esum, o);

    if (j == 0) {
        float lse = vmax + logf(esum);
        float s0 = g_S[((size_t)0 * BB + bq) * BB + bq];
        float s1 = g_S[((size_t)1 * BB + bq) * BB + bq];
        float ce_t = lse - s0;
        float m2   = fmaxf(s0, s1);
        float lse2 = m2 + logf(expf(s0 - m2) + expf(s1 - m2));
        float l0 = labels[bq * NN + 0];
        float l1 = labels[bq * NN + 1];
        float kl_t = expf(l0) * (l0 - (s0 - lse2)) + expf(l1) * (l1 - (s1 - lse2));
        s_loss[bq] = kl_t + 0.5f * ce_t;
    }
    __syncthreads();
    if (tid < 64) {
        float v = s_loss[tid];
        #pragma unroll
        for (int o = 16; o; o >>= 1) v += __shfl_xor_sync(0xffffffffu, v, o);
        if ((tid & 31) == 0) red[tid >> 5] = v;
    }
    __syncthreads();
    if (tid == 0) out[0] = (red[0] + red[1]) / (float)BB;
}

// ---------------------------------------------------------------------------
extern "C" void kernel_launch(void* const* d_in, const int* in_sizes, int n_in,
                              void* d_out, int out_size) {
    const float* q_reps  = (const float*)d_in[0];   // [B, Lq, D]
    const float* d_reps  = (const float*)d_in[1];   // [N, B, Ld, D]
    const int*   d_masks = (const int*)d_in[2];     // [N, B, Ld]
    const float* labels  = (const float*)d_in[3];   // [B, N]
    float* out = (float*)d_out;

    qnorm_kernel<<<(BB * LQ) / 8, 256>>>(q_reps);
    dinv_kernel<<<NN * BB, 512>>>(d_reps, d_masks);

    cudaFuncSetAttribute(maxsim_kernel,
                         cudaFuncAttributeMaxDynamicSharedMemorySize, SMEM_TOTAL);
    maxsim_kernel<<<NN * BB, 256, SMEM_TOTAL>>>(d_reps, d_masks);

    finalize_kernel<<<1, 512>>>(labels, out);
}